// round 10
// baseline (speedup 1.0000x reference)
#include <cuda_runtime.h>
#include <cstdint>

// ---------------------------------------------------------------------------
// y = EqualizedConv2d(stride=2, 3x3, 256->512, 1/48)( blur4x4(x) ) + bias
// Round 10: dual-limb INT8 IMMA path.
//   xb, w~ quantized to 15-bit fixed point, split into 2 s8 limbs.
//   y = qa*qw*( 2^14 * S11 + 2^7 * (S10 + S01) )  (A0*W0 term dropped)
//   GEMM M=65536 N=512 K=2304 via mma.sync.m16n8k32.s8 (3 IMMAs per K=32).
//   A gathered fragment-direct from phase-interleaved s8 planes (no smem!).
// ---------------------------------------------------------------------------

#define NIMG   16
#define CIN    256
#define HIN    128
#define COUT   512
#define KDIM   2304
#define MDIM   65536
#define HP     65
#define XPITCH 68                          // padded phase-grid row (x' dim)
#define CSTRIDE (HP * XPITCH)              // 4420 u32 per (nc)
#define NSTRIDE (CIN * CSTRIDE)            // 1,131,520 u32 per image
#define PLANE_U32 ((size_t)NIMG * NSTRIDE) // 18,104,320 u32 (72.4 MB)

#define INV_QA 6500.0f
#define INV_QW 130000.0f
#define QMAX   16319

// Scratch
__device__ int   g_xq1[PLANE_U32];     // hi-limb plane (bytes, phase-interleaved)
__device__ int   g_xq0[PLANE_U32];     // lo-limb plane
__device__ uint2 g_Bq[294912];         // packed B fragments (2.36 MB, L2-hot)
__device__ float g_k[4];               // separable 1-D taps

// ---------------------------------------------------------------------------
// Kernel 0: 1-D taps (row sums of the normalized outer-product kernel; exact)
// ---------------------------------------------------------------------------
__global__ void prep_k_kernel(const float* __restrict__ bk) {
    if (threadIdx.x < 4) {
        int t = threadIdx.x;
        g_k[t] = bk[t*4+0] + bk[t*4+1] + bk[t*4+2] + bk[t*4+3];
    }
}

// ---------------------------------------------------------------------------
// k-slot enumeration (shared convention between bprep and the GEMM):
//   quads 0..255   : type0, c = q,        pos p -> (kh,kw) = (p>>1, p&1)
//   quads 256..511 : type1, c = q-256,    pos p -> {(0,2),(1,2),(2,0),(2,1)}[p]
//   quads 512..575 : type2, c = (q-512)*4+p, tap (2,2)
// chunk kc covers quads 8kc..8kc+7; lane tg owns quads tg (b0/a0,a1) and tg+4.
// ---------------------------------------------------------------------------
__device__ __forceinline__ void slot_to_ckk(int Q, int pos, int& c, int& kh, int& kw) {
    if (Q < 256)      { c = Q;            kh = pos >> 1;  kw = pos & 1; }
    else if (Q < 512) { c = Q - 256;
                        const int khs[4] = {0,1,2,2}, kws[4] = {2,2,0,1};
                        kh = khs[pos]; kw = kws[pos]; }
    else              { c = (Q - 512) * 4 + pos; kh = 2; kw = 2; }
}

// ---------------------------------------------------------------------------
// Kernel 1: fused separable 4x4 blur -> quantized dual-limb phase planes.
// ---------------------------------------------------------------------------
__global__ void __launch_bounds__(256) blur_kernel(const float* __restrict__ x) {
    __shared__ float xs[35 * 128];
    __shared__ float hs[35 * 132];

    const int nc  = blockIdx.x;
    const int q   = blockIdx.y;
    const int tid = threadIdx.x;

    const int i0   = (q == 0) ? 0 : (q == 1) ? 33 : (q == 2) ? 65 : 97;
    const int icnt = (q == 0) ? 33 : 32;
    int in_lo = i0 - 2;          if (in_lo < 0)   in_lo = 0;
    int in_hi = i0 + icnt + 1;   if (in_hi > 128) in_hi = 128;
    const int nrows = in_hi - in_lo;

    const float k0 = g_k[0], k1 = g_k[1], k2 = g_k[2], k3 = g_k[3];

    {
        const float4* src = (const float4*)(x + ((size_t)nc * HIN + in_lo) * HIN);
        float4* dst = (float4*)xs;
        for (int t = tid; t < nrows * 32; t += 256) dst[t] = src[t];
    }
    __syncthreads();

    for (int t = tid; t < nrows * 129; t += 256) {
        int j = t % 129, rr = t / 129;
        const float* xr = xs + rr * 128;
        float acc = 0.f;
        int c = j - 2;
        if ((unsigned)(c    ) < 128u) acc += k0 * xr[c];
        if ((unsigned)(c + 1) < 128u) acc += k1 * xr[c + 1];
        if ((unsigned)(c + 2) < 128u) acc += k2 * xr[c + 2];
        if ((unsigned)(c + 3) < 128u) acc += k3 * xr[c + 3];
        hs[rr * 132 + j] = acc;
    }
    __syncthreads();

    char* p1 = (char*)g_xq1;
    char* p0 = (char*)g_xq0;
    const size_t base_nc = (size_t)nc * CSTRIDE;
    for (int t = tid; t < icnt * 129; t += 256) {
        int j = t % 129, io = t / 129;
        int i = i0 + io;
        int r = i - 2;
        float acc = 0.f;
        if ((unsigned)(r    ) < 128u) acc += k0 * hs[(r     - in_lo) * 132 + j];
        if ((unsigned)(r + 1) < 128u) acc += k1 * hs[(r + 1 - in_lo) * 132 + j];
        if ((unsigned)(r + 2) < 128u) acc += k2 * hs[(r + 2 - in_lo) * 132 + j];
        if ((unsigned)(r + 3) < 128u) acc += k3 * hs[(r + 3 - in_lo) * 132 + j];
        int A = (int)rintf(acc * INV_QA);
        A = max(-QMAX, min(QMAX, A));
        int A1 = (A + 64) >> 7;
        int A0 = A - (A1 << 7);
        int ph = (i & 1) * 2 + (j & 1);
        size_t bidx = ((base_nc + (size_t)(i >> 1) * XPITCH + (j >> 1)) << 2) + ph;
        p1[bidx] = (char)A1;
        p0[bidx] = (char)A0;
    }
}

// ---------------------------------------------------------------------------
// Kernel 2: pack B fragments.
// g_Bq[(((nt*72+kc)*4+wn)*4+ni)*2+limb][lane] = uint2{b0,b1}
//   b0 bytes j = k-slot 4tg+j ; b1 bytes j = k-slot 4tg+16+j ; n = nt*128+wn*32+ni*8+g
//   limb0 = W1 (hi), limb1 = W0 (lo)
// ---------------------------------------------------------------------------
__global__ void bprep_kernel(const float* __restrict__ w) {
    int idx = blockIdx.x * 256 + threadIdx.x;     // < 294912
    if (idx >= 294912) return;
    int lane = idx & 31;
    int limb = (idx >> 5) & 1;
    int ni   = (idx >> 6) & 3;
    int wn   = (idx >> 8) & 3;
    int rest = idx >> 10;
    int kc   = rest % 72;
    int nt   = rest / 72;
    int g  = lane >> 2;
    int tg = lane & 3;
    int n = nt * 128 + wn * 32 + ni * 8 + g;

    unsigned words[2];
#pragma unroll
    for (int h = 0; h < 2; ++h) {
        int Q = kc * 8 + tg + 4 * h;
        unsigned pack = 0;
#pragma unroll
        for (int pos = 0; pos < 4; ++pos) {
            int c, kh, kw;
            slot_to_ckk(Q, pos, c, kh, kw);
            float wv = w[((size_t)n * CIN + c) * 9 + kh * 3 + kw] * (1.0f / 48.0f);
            int W = (int)rintf(wv * INV_QW);
            W = max(-QMAX, min(QMAX, W));
            int W1 = (W + 64) >> 7;
            int W0 = W - (W1 << 7);
            int b = limb ? W0 : W1;
            pack |= ((unsigned)(b & 255)) << (pos * 8);
        }
        words[h] = pack;
    }
    g_Bq[idx] = make_uint2(words[0], words[1]);
}

// ---------------------------------------------------------------------------
// Kernel 3: INT8 dual-limb IMMA GEMM, fragment-direct A gather, no smem.
// grid (4 n-tiles, 1024 m-tiles), 256 thr, 8 warps: warpm = w&1 (32m),
// wn = w>>1 (32n). Warp tile 32x64? -> 32(m) x 32(n): mi 0..1, ni 0..3.
// ---------------------------------------------------------------------------
#define IMMA(acc, a, b0, b1)                                                   \
    asm volatile(                                                              \
        "mma.sync.aligned.m16n8k32.row.col.s32.s8.s8.s32 "                     \
        "{%0,%1,%2,%3}, {%4,%5,%6,%7}, {%8,%9}, {%0,%1,%2,%3};\n"              \
        : "+r"((acc)[0]), "+r"((acc)[1]), "+r"((acc)[2]), "+r"((acc)[3])       \
        : "r"((a)[0]), "r"((a)[1]), "r"((a)[2]), "r"((a)[3]),                  \
          "r"(b0), "r"(b1))

__global__ void __launch_bounds__(256, 2)
imma_kernel(const float* __restrict__ bias, float* __restrict__ out) {
    const int tid  = threadIdx.x;
    const int warp = tid >> 5;
    const int lane = tid & 31;
    const int g    = lane >> 2;
    const int tg   = lane & 3;
    const int warpm = warp & 1;
    const int wn    = warp >> 1;
    const int nt    = blockIdx.x;
    const int mbase = blockIdx.y * 64 + warpm * 32;

    // per-lane plane offsets (u32 units) for rows (mi, r): m = mbase+mi*16+g+8r
    int moff[2][2];
#pragma unroll
    for (int mi = 0; mi < 2; ++mi)
#pragma unroll
        for (int r = 0; r < 2; ++r) {
            int m = mbase + mi * 16 + g + 8 * r;
            moff[mi][r] = (m >> 12) * NSTRIDE + ((m >> 6) & 63) * XPITCH + (m & 63);
        }

    const int* __restrict__ P1 = g_xq1;
    const int* __restrict__ P0 = g_xq0;
    const uint2* __restrict__ Bt = g_Bq + nt * 73728 + wn * 256 + lane;

    int accH[2][4][4], accC[2][4][4];
#pragma unroll
    for (int mi = 0; mi < 2; ++mi)
#pragma unroll
        for (int ni = 0; ni < 4; ++ni)
#pragma unroll
            for (int c = 0; c < 4; ++c) { accH[mi][ni][c] = 0; accC[mi][ni][c] = 0; }

    unsigned A1f[2][4], A0f[2][4];
    unsigned Bhi[4][2], Blo[4][2];

#define LOAD_B(KC)                                                             \
    {                                                                          \
        const uint2* bp = Bt + (KC) * 1024;                                    \
        _Pragma("unroll")                                                      \
        for (int ni = 0; ni < 4; ++ni) {                                       \
            uint2 h_ = bp[ni * 64];                                            \
            uint2 l_ = bp[ni * 64 + 32];                                       \
            Bhi[ni][0] = h_.x; Bhi[ni][1] = h_.y;                              \
            Blo[ni][0] = l_.x; Blo[ni][1] = l_.y;                              \
        }                                                                      \
    }

#define DO_MMAS()                                                              \
    _Pragma("unroll")                                                          \
    for (int mi = 0; mi < 2; ++mi)                                             \
        _Pragma("unroll")                                                      \
        for (int ni = 0; ni < 4; ++ni) {                                       \
            IMMA(accH[mi][ni], A1f[mi], Bhi[ni][0], Bhi[ni][1]);               \
            IMMA(accC[mi][ni], A1f[mi], Blo[ni][0], Blo[ni][1]);               \
            IMMA(accC[mi][ni], A0f[mi], Bhi[ni][0], Bhi[ni][1]);               \
        }

    // ---- chunks 0..31: type0 quads (4-phase u32 loads) ----
#pragma unroll 2
    for (int kc = 0; kc < 32; ++kc) {
        int cb0 = (kc * 8 + tg) * CSTRIDE;
        int cb1 = cb0 + 4 * CSTRIDE;
#pragma unroll
        for (int mi = 0; mi < 2; ++mi) {
            A1f[mi][0] = P1[moff[mi][0] + cb0];
            A1f[mi][1] = P1[moff[mi][1] + cb0];
            A1f[mi][2] = P1[moff[mi][0] + cb1];
            A1f[mi][3] = P1[moff[mi][1] + cb1];
            A0f[mi][0] = P0[moff[mi][0] + cb0];
            A0f[mi][1] = P0[moff[mi][1] + cb0];
            A0f[mi][2] = P0[moff[mi][0] + cb1];
            A0f[mi][3] = P0[moff[mi][1] + cb1];
        }
        LOAD_B(kc);
        DO_MMAS();
    }

    // ---- chunks 32..63: type1 quads (two u32 + PRMT) ----
#pragma unroll 2
    for (int kc = 32; kc < 64; ++kc) {
        int cA = ((kc - 32) * 8 + tg) * CSTRIDE;
        int cB = cA + 4 * CSTRIDE;
#pragma unroll
        for (int mi = 0; mi < 2; ++mi)
#pragma unroll
            for (int r = 0; r < 2; ++r) {
                int oA = moff[mi][r] + cA;
                int oB = moff[mi][r] + cB;
                A1f[mi][r]     = __byte_perm(P1[oA + 1], P1[oA + XPITCH], 0x5420);
                A1f[mi][2 + r] = __byte_perm(P1[oB + 1], P1[oB + XPITCH], 0x5420);
                A0f[mi][r]     = __byte_perm(P0[oA + 1], P0[oA + XPITCH], 0x5420);
                A0f[mi][2 + r] = __byte_perm(P0[oB + 1], P0[oB + XPITCH], 0x5420);
            }
        LOAD_B(kc);
        DO_MMAS();
    }

    // ---- chunks 64..71: type2 quads (four u32 byte0 + PRMT) ----
    for (int kc = 64; kc < 72; ++kc) {
        int cA = (((kc - 64) * 8 + tg) * 4) * CSTRIDE;
        int cB = cA + 16 * CSTRIDE;
#pragma unroll
        for (int mi = 0; mi < 2; ++mi)
#pragma unroll
            for (int r = 0; r < 2; ++r) {
                int oA = moff[mi][r] + cA + XPITCH + 1;
                int oB = moff[mi][r] + cB + XPITCH + 1;
                {
                    unsigned t0 = __byte_perm(P1[oA], P1[oA + CSTRIDE], 0x0040);
                    unsigned t1 = __byte_perm(P1[oA + 2*CSTRIDE], P1[oA + 3*CSTRIDE], 0x0040);
                    A1f[mi][r] = __byte_perm(t0, t1, 0x5410);
                    unsigned s0 = __byte_perm(P0[oA], P0[oA + CSTRIDE], 0x0040);
                    unsigned s1 = __byte_perm(P0[oA + 2*CSTRIDE], P0[oA + 3*CSTRIDE], 0x0040);
                    A0f[mi][r] = __byte_perm(s0, s1, 0x5410);
                }
                {
                    unsigned t0 = __byte_perm(P1[oB], P1[oB + CSTRIDE], 0x0040);
                    unsigned t1 = __byte_perm(P1[oB + 2*CSTRIDE], P1[oB + 3*CSTRIDE], 0x0040);
                    A1f[mi][2 + r] = __byte_perm(t0, t1, 0x5410);
                    unsigned s0 = __byte_perm(P0[oB], P0[oB + CSTRIDE], 0x0040);
                    unsigned s1 = __byte_perm(P0[oB + 2*CSTRIDE], P0[oB + 3*CSTRIDE], 0x0040);
                    A0f[mi][2 + r] = __byte_perm(s0, s1, 0x5410);
                }
            }
        LOAD_B(kc);
        DO_MMAS();
    }

    // ---- epilogue: y = SH*accH + SC*accC + bias ----
    const float SH = 16384.0f / (INV_QA * INV_QW);
    const float SC = 128.0f   / (INV_QA * INV_QW);
#pragma unroll
    for (int mi = 0; mi < 2; ++mi) {
        int mg   = mbase + mi * 16 + g;
        int n16  = mg >> 12;
        int rem  = mg & 4095;
#pragma unroll
        for (int ni = 0; ni < 4; ++ni) {
            int oc = nt * 128 + wn * 32 + ni * 8 + tg * 2;
            float bv0 = __ldg(&bias[oc]);
            float bv1 = __ldg(&bias[oc + 1]);
            float* p = out + (((size_t)(n16 * COUT + oc)) << 12) + rem;
            p[0]    = (float)accH[mi][ni][0] * SH + (float)accC[mi][ni][0] * SC + bv0;
            p[4096] = (float)accH[mi][ni][1] * SH + (float)accC[mi][ni][1] * SC + bv1;
            p[8]    = (float)accH[mi][ni][2] * SH + (float)accC[mi][ni][2] * SC + bv0;
            p[4104] = (float)accH[mi][ni][3] * SH + (float)accC[mi][ni][3] * SC + bv1;
        }
    }
#undef LOAD_B
#undef DO_MMAS
}

// ---------------------------------------------------------------------------
extern "C" void kernel_launch(void* const* d_in, const int* in_sizes, int n_in,
                              void* d_out, int out_size) {
    const float* x    = (const float*)d_in[0];
    const float* w    = (const float*)d_in[1];
    const float* bias = (const float*)d_in[2];
    const float* bk   = (const float*)d_in[3];
    float* out = (float*)d_out;
    (void)in_sizes; (void)n_in; (void)out_size;

    prep_k_kernel<<<1, 32>>>(bk);

    blur_kernel<<<dim3(NIMG * CIN, 4), 256>>>(x);

    bprep_kernel<<<294912 / 256, 256>>>(w);

    dim3 grid(COUT / 128, MDIM / 64);       // (4, 1024), n fast: B table L2-hot
    imma_kernel<<<grid, 256>>>(bias, out);
}

// round 12
// speedup vs baseline: 2.4095x; 2.4095x over previous
#include <cuda_runtime.h>
#include <cstdint>

// ---------------------------------------------------------------------------
// y = EqualizedConv2d(stride=2, 3x3, 256->512, 1/48)( blur4x4(x) ) + bias
// Round 11: tf32 mma.sync GEMM, fragment-direct gmem gathers (no smem, no
// syncs in mainloop — the structure that gave 96.7% tensor busy in R10),
// fed by fused separable blur into tf32-pre-rounded phase-split planes.
//   M=65536, N=512, K=2304.  Block 128x128, warp 32x64, 2 CTAs/SM.
// ---------------------------------------------------------------------------

#define NIMG   16
#define CIN    256
#define HIN    128
#define COUT   512
#define KDIM   2304
#define MDIM   65536
#define HPW    68                 // padded phase row width (65 valid)
#define CROW   4420               // 65*68 floats per (nc, phase)
#define NBLK2  1131520            // 256*CROW (per image within phase)
#define PHBLK  18104320           // 16*NBLK2 (per phase)
#define NKC    288                // K / 8 chunks

// Scratch (__device__ globals only)
__device__ float  g_xp[(size_t)4 * PHBLK];     // phase-split blurred, tf32-rounded
__device__ float2 g_Bf[(size_t)4 * NKC * 16 * 32];  // packed B fragments (4.7 MB)
__device__ int    g_P[KDIM];                   // per-k phase offsets
__device__ float  g_k[4];                      // separable 1-D taps

__device__ __forceinline__ float tf32_round(float v) {
    unsigned o;
    asm("cvt.rna.tf32.f32 %0, %1;" : "=r"(o) : "f"(v));
    return __uint_as_float(o);
}

// ---------------------------------------------------------------------------
// Kernel 0a: 1-D taps (row sums of the normalized outer-product kernel; exact)
// ---------------------------------------------------------------------------
__global__ void prep_k_kernel(const float* __restrict__ bk) {
    if (threadIdx.x < 4) {
        int t = threadIdx.x;
        g_k[t] = bk[t*4+0] + bk[t*4+1] + bk[t*4+2] + bk[t*4+3];
    }
}

// Kernel 0b: per-k phase offsets.  k = c*9 + kh*3 + kw
__global__ void prep_P_kernel() {
    int k = blockIdx.x * 256 + threadIdx.x;
    if (k >= KDIM) return;
    int c  = k / 9, rem = k - 9 * c;
    int kh = rem / 3, kw = rem - 3 * kh;
    int ph = (kh & 1) * 2 + (kw & 1);
    g_P[k] = ph * PHBLK + c * CROW + (kh >> 1) * HPW + (kw >> 1);
}

// ---------------------------------------------------------------------------
// Kernel 1: fused separable 4x4 blur -> phase-split planes, tf32-rounded.
// ---------------------------------------------------------------------------
__global__ void __launch_bounds__(256) blur_kernel(const float* __restrict__ x) {
    __shared__ float xs[35 * 128];
    __shared__ float hs[35 * 132];

    const int nc  = blockIdx.x;
    const int q   = blockIdx.y;
    const int tid = threadIdx.x;

    const int i0   = (q == 0) ? 0 : (q == 1) ? 33 : (q == 2) ? 65 : 97;
    const int icnt = (q == 0) ? 33 : 32;
    int in_lo = i0 - 2;          if (in_lo < 0)   in_lo = 0;
    int in_hi = i0 + icnt + 1;   if (in_hi > 128) in_hi = 128;
    const int nrows = in_hi - in_lo;

    const float k0 = g_k[0], k1 = g_k[1], k2 = g_k[2], k3 = g_k[3];

    {
        const float4* src = (const float4*)(x + ((size_t)nc * HIN + in_lo) * HIN);
        float4* dst = (float4*)xs;
        for (int t = tid; t < nrows * 32; t += 256) dst[t] = src[t];
    }
    __syncthreads();

    for (int t = tid; t < nrows * 129; t += 256) {
        int j = t % 129, rr = t / 129;
        const float* xr = xs + rr * 128;
        float acc = 0.f;
        int c = j - 2;
        if ((unsigned)(c    ) < 128u) acc += k0 * xr[c];
        if ((unsigned)(c + 1) < 128u) acc += k1 * xr[c + 1];
        if ((unsigned)(c + 2) < 128u) acc += k2 * xr[c + 2];
        if ((unsigned)(c + 3) < 128u) acc += k3 * xr[c + 3];
        hs[rr * 132 + j] = acc;
    }
    __syncthreads();

    const int base_nc = nc * CROW;
    for (int t = tid; t < icnt * 129; t += 256) {
        int j = t % 129, io = t / 129;
        int i = i0 + io;
        int r = i - 2;
        float acc = 0.f;
        if ((unsigned)(r    ) < 128u) acc += k0 * hs[(r     - in_lo) * 132 + j];
        if ((unsigned)(r + 1) < 128u) acc += k1 * hs[(r + 1 - in_lo) * 132 + j];
        if ((unsigned)(r + 2) < 128u) acc += k2 * hs[(r + 2 - in_lo) * 132 + j];
        if ((unsigned)(r + 3) < 128u) acc += k3 * hs[(r + 3 - in_lo) * 132 + j];
        int ph = (i & 1) * 2 + (j & 1);
        g_xp[ph * PHBLK + base_nc + (i >> 1) * HPW + (j >> 1)] = tf32_round(acc);
    }
}

// ---------------------------------------------------------------------------
// Kernel 2: B fragment table.
// g_Bf[(((nt*288 + kc)*16 + nj)*32) + lane] = { B[kc*8+tg][n], B[kc*8+tg+4][n] }
//   where n = nt*128 + nj*8 + (lane>>2), tg = lane&3,
//   B[k][n] = tf32( weight[n][k] / 48 ),  k = c*9+kh*3+kw (natural order).
// ---------------------------------------------------------------------------
__global__ void bprep_kernel(const float* __restrict__ w) {
    int idx = blockIdx.x * 256 + threadIdx.x;        // < 589824
    int lane = idx & 31;
    int nj   = (idx >> 5) & 15;
    int rest = idx >> 9;
    int kc   = rest % NKC;
    int nt   = rest / NKC;
    int n = nt * 128 + nj * 8 + (lane >> 2);
    int k = kc * 8 + (lane & 3);
    const float s = 1.0f / 48.0f;
    float2 v;
    v.x = tf32_round(w[(size_t)n * KDIM + k]     * s);
    v.y = tf32_round(w[(size_t)n * KDIM + k + 4] * s);
    g_Bf[idx] = v;
}

// ---------------------------------------------------------------------------
// Kernel 3: tf32 GEMM, fragment-direct gathers, zero smem, zero mainloop syncs.
// grid (4 n-tiles, 512 m-tiles), 256 thr, 8 warps = 4(m) x 2(n), warp 32x64.
// ---------------------------------------------------------------------------
#define MMA_TF32(acc, a, b0, b1)                                               \
    asm volatile(                                                              \
        "mma.sync.aligned.m16n8k8.row.col.f32.tf32.tf32.f32 "                  \
        "{%0,%1,%2,%3}, {%4,%5,%6,%7}, {%8,%9}, {%0,%1,%2,%3};\n"              \
        : "+f"((acc)[0]), "+f"((acc)[1]), "+f"((acc)[2]), "+f"((acc)[3])       \
        : "r"(__float_as_uint((a)[0])), "r"(__float_as_uint((a)[1])),          \
          "r"(__float_as_uint((a)[2])), "r"(__float_as_uint((a)[3])),          \
          "r"(__float_as_uint(b0)), "r"(__float_as_uint(b1)))

__global__ void __launch_bounds__(256, 2)
gemm_kernel(const float* __restrict__ bias, float* __restrict__ out) {
    const int tid   = threadIdx.x;
    const int warp  = tid >> 5;
    const int lane  = tid & 31;
    const int g     = lane >> 2;
    const int tg    = lane & 3;
    const int warpm = warp & 3;
    const int wn    = warp >> 2;
    const int nt    = blockIdx.x;
    const int m0    = blockIdx.y << 7;

    // plane offsets for the two m16 tiles (row r=0; r=1 is +8, never crosses ow row)
    int moff[2];
#pragma unroll
    for (int mi = 0; mi < 2; ++mi) {
        int m = m0 + warpm * 32 + mi * 16 + g;
        moff[mi] = (m >> 12) * NBLK2 + ((m >> 6) & 63) * HPW + (m & 63);
    }

    const float*  __restrict__ xp = g_xp;
    const float2* __restrict__ Bt =
        g_Bf + ((size_t)(nt * NKC * 16 + wn * 8) << 5) + lane;

    float acc[2][8][4];
#pragma unroll
    for (int a = 0; a < 2; ++a)
#pragma unroll
        for (int b = 0; b < 8; ++b)
#pragma unroll
            for (int c = 0; c < 4; ++c) acc[a][b][c] = 0.f;

    float  aF[2][2][4];
    float2 bF[2][8];

#define LOAD_CHUNK(KC, S)                                                      \
    {                                                                          \
        int p0_ = g_P[(KC) * 8 + tg];                                          \
        int p1_ = g_P[(KC) * 8 + tg + 4];                                      \
        _Pragma("unroll")                                                      \
        for (int mi = 0; mi < 2; ++mi) {                                       \
            aF[S][mi][0] = xp[moff[mi] + p0_];                                 \
            aF[S][mi][1] = xp[moff[mi] + 8 + p0_];                             \
            aF[S][mi][2] = xp[moff[mi] + p1_];                                 \
            aF[S][mi][3] = xp[moff[mi] + 8 + p1_];                             \
        }                                                                      \
        const float2* bp_ = Bt + ((size_t)(KC) << 9);                          \
        _Pragma("unroll")                                                      \
        for (int ni = 0; ni < 8; ++ni) bF[S][ni] = bp_[ni * 32];               \
    }

    LOAD_CHUNK(0, 0);

#pragma unroll 2
    for (int kc = 0; kc < NKC; ++kc) {
        const int s = kc & 1;
        if (kc + 1 < NKC) LOAD_CHUNK(kc + 1, s ^ 1);
#pragma unroll
        for (int ni = 0; ni < 8; ++ni) {
#pragma unroll
            for (int mi = 0; mi < 2; ++mi)
                MMA_TF32(acc[mi][ni], aF[s][mi], bF[s][ni].x, bF[s][ni].y);
        }
    }
#undef LOAD_CHUNK

    // epilogue: D[m][oc] -> out[n, oc, oh, ow] + bias
#pragma unroll
    for (int mi = 0; mi < 2; ++mi) {
        int m   = m0 + warpm * 32 + mi * 16 + g;
        int n16 = m >> 12;
        int rem = m & 4095;
#pragma unroll
        for (int ni = 0; ni < 8; ++ni) {
            int oc = nt * 128 + wn * 64 + ni * 8 + tg * 2;
            float bv0 = __ldg(&bias[oc]);
            float bv1 = __ldg(&bias[oc + 1]);
            float* p = out + (((size_t)(n16 * COUT + oc)) << 12) + rem;
            p[0]    = acc[mi][ni][0] + bv0;   // (m,   oc)
            p[4096] = acc[mi][ni][1] + bv1;   // (m,   oc+1)
            p[8]    = acc[mi][ni][2] + bv0;   // (m+8, oc)
            p[4104] = acc[mi][ni][3] + bv1;   // (m+8, oc+1)
        }
    }
}

// ---------------------------------------------------------------------------
extern "C" void kernel_launch(void* const* d_in, const int* in_sizes, int n_in,
                              void* d_out, int out_size) {
    const float* x    = (const float*)d_in[0];
    const float* w    = (const float*)d_in[1];
    const float* bias = (const float*)d_in[2];
    const float* bk   = (const float*)d_in[3];
    float* out = (float*)d_out;
    (void)in_sizes; (void)n_in; (void)out_size;

    prep_k_kernel<<<1, 32>>>(bk);
    prep_P_kernel<<<(KDIM + 255) / 256, 256>>>();

    blur_kernel<<<dim3(NIMG * CIN, 4), 256>>>(x);

    bprep_kernel<<<(4 * NKC * 16 * 32) / 256, 256>>>(w);

    dim3 grid(COUT / 128, MDIM / 128);      // (4, 512): n fast -> A L2 reuse
    gemm_kernel<<<grid, 256>>>(bias, out);
}

// round 13
// speedup vs baseline: 4.2452x; 1.7619x over previous
#include <cuda_runtime.h>
#include <cuda_fp16.h>
#include <cstdint>

// ---------------------------------------------------------------------------
// y = EqualizedConv2d(stride=2, 3x3, 256->512, 1/48)( blur4x4(x) ) + bias
// Round 13: fp16 m16n8k16 mma.sync GEMM, fragment-direct gmem gathers
// (no smem / no sync mainloop), fed by fused separable blur emitting fp16
// PHASE-PAIR planes so each A fragment register is ONE 32-bit load.
//   M=65536, N=512, K=2304 = 144 k16-chunks (128 main + 16 tail).
// ---------------------------------------------------------------------------

#define NIMG   16
#define CIN    256
#define HIN    128
#define COUT   512
#define KDIM   2304
#define MDIM   65536
#define XPW    66                  // pair-plane row pitch (65 valid x')
#define CPOS   4290                // 65*66 positions per (n,c)
#define NPOS   1098240             // 256*CPOS per image
#define NKC    144                 // k16 chunks (128 main + 16 tail)

// Scratch: three fp16 phase-pair planes (each slot = 2 halves = 4B)
//  P01[pos] = { xb(2y,2x),   xb(2y,2x+1) }      (ph0, ph1)
//  P23[pos] = { xb(2y+1,2x), xb(2y+1,2x+1) }    (ph2, ph3)
//  P02[pos] = { xb(2y,2x),   xb(2y+1,2x) }      (ph0, ph2)
__device__ __half g_P01h[(size_t)4096 * CPOS * 2];
__device__ __half g_P23h[(size_t)4096 * CPOS * 2];
__device__ __half g_P02h[(size_t)4096 * CPOS * 2];
__device__ uint4  g_Bq4[4 * NKC * 8 * 32];      // 2.36 MB fragment table
__device__ float  g_k[4];                       // separable 1-D taps

// tap order within a channel: sigma = [0,1,3,4,6,7,2,5]
__device__ __constant__ int c_sigma[8] = {0, 1, 3, 4, 6, 7, 2, 5};

// ---------------------------------------------------------------------------
// Kernel 0: 1-D taps (row sums of normalized outer-product kernel; exact)
// ---------------------------------------------------------------------------
__global__ void prep_k_kernel(const float* __restrict__ bk) {
    if (threadIdx.x < 4) {
        int t = threadIdx.x;
        g_k[t] = bk[t*4+0] + bk[t*4+1] + bk[t*4+2] + bk[t*4+3];
    }
}

// ---------------------------------------------------------------------------
// Kernel 1: fused separable 4x4 blur -> fp16 phase-pair planes.
// ---------------------------------------------------------------------------
__global__ void __launch_bounds__(256) blur_kernel(const float* __restrict__ x) {
    __shared__ float xs[35 * 128];
    __shared__ float hs[35 * 132];

    const int nc  = blockIdx.x;
    const int q   = blockIdx.y;
    const int tid = threadIdx.x;

    const int i0   = (q == 0) ? 0 : (q == 1) ? 33 : (q == 2) ? 65 : 97;
    const int icnt = (q == 0) ? 33 : 32;
    int in_lo = i0 - 2;          if (in_lo < 0)   in_lo = 0;
    int in_hi = i0 + icnt + 1;   if (in_hi > 128) in_hi = 128;
    const int nrows = in_hi - in_lo;

    const float k0 = g_k[0], k1 = g_k[1], k2 = g_k[2], k3 = g_k[3];

    {
        const float4* src = (const float4*)(x + ((size_t)nc * HIN + in_lo) * HIN);
        float4* dst = (float4*)xs;
        for (int t = tid; t < nrows * 32; t += 256) dst[t] = src[t];
    }
    __syncthreads();

    for (int t = tid; t < nrows * 129; t += 256) {
        int j = t % 129, rr = t / 129;
        const float* xr = xs + rr * 128;
        float acc = 0.f;
        int c = j - 2;
        if ((unsigned)(c    ) < 128u) acc += k0 * xr[c];
        if ((unsigned)(c + 1) < 128u) acc += k1 * xr[c + 1];
        if ((unsigned)(c + 2) < 128u) acc += k2 * xr[c + 2];
        if ((unsigned)(c + 3) < 128u) acc += k3 * xr[c + 3];
        hs[rr * 132 + j] = acc;
    }
    __syncthreads();

    const int base_nc = nc * CPOS;
    for (int t = tid; t < icnt * 129; t += 256) {
        int j = t % 129, io = t / 129;
        int i = i0 + io;
        int r = i - 2;
        float acc = 0.f;
        if ((unsigned)(r    ) < 128u) acc += k0 * hs[(r     - in_lo) * 132 + j];
        if ((unsigned)(r + 1) < 128u) acc += k1 * hs[(r + 1 - in_lo) * 132 + j];
        if ((unsigned)(r + 2) < 128u) acc += k2 * hs[(r + 2 - in_lo) * 132 + j];
        if ((unsigned)(r + 3) < 128u) acc += k3 * hs[(r + 3 - in_lo) * 132 + j];
        __half v = __float2half_rn(acc);
        int pos = base_nc + (i >> 1) * XPW + (j >> 1);
        if ((i & 1) == 0) g_P01h[pos * 2 + (j & 1)] = v;
        else              g_P23h[pos * 2 + (j & 1)] = v;
        if ((j & 1) == 0) g_P02h[pos * 2 + (i & 1)] = v;
    }
}

// ---------------------------------------------------------------------------
// Kernel 2: B fragment table (fp16, scaled).
// idx = ((nt*144 + kc)*8 + qp)*32 + lane -> uint4 { b0(2qp), b1(2qp),
//        b0(2qp+1), b1(2qp+1) } where ni in [0,16): n = nt*128 + ni*8 + g.
// Main kc (<128): b0 halves = W~[c0, sig(2tg)], W~[c0, sig(2tg+1)], c0 = 2kc;
//                 b1 same taps at c1 = 2kc+1.
// Tail kc (>=128): tb = (kc-128)*16;
//                 b0 halves = W~[tb+2tg, 8], W~[tb+2tg+1, 8];
//                 b1 halves = W~[tb+8+2tg, 8], W~[tb+8+2tg+1, 8].
// ---------------------------------------------------------------------------
__global__ void bprep_kernel(const float* __restrict__ w) {
    int idx = blockIdx.x * 256 + threadIdx.x;      // < 147456
    if (idx >= 4 * NKC * 8 * 32) return;
    int lane = idx & 31;
    int qp   = (idx >> 5) & 7;
    int rest = idx >> 8;
    int kc   = rest % NKC;
    int nt   = rest / NKC;
    int g  = lane >> 2;
    int tg = lane & 3;
    const float s = 1.0f / 48.0f;

    unsigned r[4];
#pragma unroll
    for (int h = 0; h < 2; ++h) {
        int ni = 2 * qp + h;
        int n  = nt * 128 + ni * 8 + g;
        const float* wn_ = w + (size_t)n * KDIM;   // [c][tap] natural order
        float b0x, b0y, b1x, b1y;
        if (kc < 128) {
            int c0 = 2 * kc, c1 = c0 + 1;
            int t0 = c_sigma[2 * tg], t1 = c_sigma[2 * tg + 1];
            b0x = wn_[c0 * 9 + t0] * s;  b0y = wn_[c0 * 9 + t1] * s;
            b1x = wn_[c1 * 9 + t0] * s;  b1y = wn_[c1 * 9 + t1] * s;
        } else {
            int tb = (kc - 128) * 16;
            b0x = wn_[(tb + 2 * tg)     * 9 + 8] * s;
            b0y = wn_[(tb + 2 * tg + 1) * 9 + 8] * s;
            b1x = wn_[(tb + 8 + 2 * tg)     * 9 + 8] * s;
            b1y = wn_[(tb + 8 + 2 * tg + 1) * 9 + 8] * s;
        }
        __half2 h0 = __halves2half2(__float2half_rn(b0x), __float2half_rn(b0y));
        __half2 h1 = __halves2half2(__float2half_rn(b1x), __float2half_rn(b1y));
        r[2 * h]     = *(unsigned*)&h0;
        r[2 * h + 1] = *(unsigned*)&h1;
    }
    g_Bq4[idx] = make_uint4(r[0], r[1], r[2], r[3]);
}

// ---------------------------------------------------------------------------
// Kernel 3: fp16 GEMM, fragment-direct gathers, zero smem, zero mainloop syncs.
// grid (4 n-tiles, 512 m-tiles), 256 thr, 8 warps = 4(m) x 2(n), warp 32x64.
// ---------------------------------------------------------------------------
#define MMA_F16(acc, a, b0, b1)                                                \
    asm volatile(                                                              \
        "mma.sync.aligned.m16n8k16.row.col.f32.f16.f16.f32 "                   \
        "{%0,%1,%2,%3}, {%4,%5,%6,%7}, {%8,%9}, {%0,%1,%2,%3};\n"              \
        : "+f"((acc)[0]), "+f"((acc)[1]), "+f"((acc)[2]), "+f"((acc)[3])       \
        : "r"((a)[0]), "r"((a)[1]), "r"((a)[2]), "r"((a)[3]),                  \
          "r"(b0), "r"(b1))

__global__ void __launch_bounds__(256, 2)
gemm_kernel(const float* __restrict__ bias, float* __restrict__ out) {
    const int tid   = threadIdx.x;
    const int warp  = tid >> 5;
    const int lane  = tid & 31;
    const int g     = lane >> 2;
    const int tg    = lane & 3;
    const int warpm = warp & 3;
    const int wn    = warp >> 2;
    const int nt    = blockIdx.x;
    const int m0    = blockIdx.y << 7;

    // lane-constant A plane + offset
    const uint32_t* pA   = (tg == 1) ? (const uint32_t*)g_P23h
                         : (tg == 3) ? (const uint32_t*)g_P02h
                                     : (const uint32_t*)g_P01h;
    const int roff = (tg == 2) ? XPW : (tg == 3) ? 1 : 0;
    const uint32_t* P01u = (const uint32_t*)g_P01h;

    // per-mi bases (m = m0 + warpm*32 + mi*16 + g; m+8 never crosses oh row)
    int abase[2], tbase[2];
#pragma unroll
    for (int mi = 0; mi < 2; ++mi) {
        int m  = m0 + warpm * 32 + mi * 16 + g;
        int bb = (m >> 12) * NPOS + ((m >> 6) & 63) * XPW + (m & 63);
        abase[mi] = bb + roff;
        tbase[mi] = bb + XPW + 1;           // tap-8 position (y+1, x+1), P01 lo
    }

    const uint4* Bt = g_Bq4 + (size_t)(nt * NKC) * 256 + wn * 128 + lane;

    float acc[2][8][4];
#pragma unroll
    for (int a = 0; a < 2; ++a)
#pragma unroll
        for (int b = 0; b < 8; ++b)
#pragma unroll
            for (int c = 0; c < 4; ++c) acc[a][b][c] = 0.f;

    unsigned aF[2][2][4];
    uint4    bF[2][4];

#define LOAD_MAIN(KC, S)                                                       \
    {                                                                          \
        const int co_ = (KC) * (2 * CPOS);                                     \
        _Pragma("unroll")                                                      \
        for (int mi = 0; mi < 2; ++mi) {                                       \
            aF[S][mi][0] = pA[abase[mi] + co_];                                \
            aF[S][mi][1] = pA[abase[mi] + co_ + 8];                            \
            aF[S][mi][2] = pA[abase[mi] + co_ + CPOS];                         \
            aF[S][mi][3] = pA[abase[mi] + co_ + CPOS + 8];                     \
        }                                                                      \
        const uint4* bp_ = Bt + (size_t)(KC) * 256;                            \
        _Pragma("unroll")                                                      \
        for (int np = 0; np < 4; ++np) bF[S][np] = bp_[np * 32];               \
    }

#define LOAD_TAIL(T, S)                                                        \
    {                                                                          \
        const int cb_ = ((T) * 16 + 2 * tg) * CPOS;                            \
        _Pragma("unroll")                                                      \
        for (int mi = 0; mi < 2; ++mi) {                                       \
            int b_ = tbase[mi] + cb_;                                          \
            unsigned v0, v1;                                                   \
            v0 = P01u[b_];              v1 = P01u[b_ + CPOS];                  \
            aF[S][mi][0] = __byte_perm(v0, v1, 0x5410);                        \
            v0 = P01u[b_ + 8];          v1 = P01u[b_ + CPOS + 8];              \
            aF[S][mi][1] = __byte_perm(v0, v1, 0x5410);                        \
            v0 = P01u[b_ + 8 * CPOS];   v1 = P01u[b_ + 9 * CPOS];              \
            aF[S][mi][2] = __byte_perm(v0, v1, 0x5410);                        \
            v0 = P01u[b_ + 8 * CPOS + 8]; v1 = P01u[b_ + 9 * CPOS + 8];        \
            aF[S][mi][3] = __byte_perm(v0, v1, 0x5410);                        \
        }                                                                      \
        const uint4* bp_ = Bt + (size_t)(128 + (T)) * 256;                     \
        _Pragma("unroll")                                                      \
        for (int np = 0; np < 4; ++np) bF[S][np] = bp_[np * 32];               \
    }

#define DO_MMAS(S)                                                             \
    _Pragma("unroll")                                                          \
    for (int np = 0; np < 4; ++np) {                                           \
        _Pragma("unroll")                                                      \
        for (int mi = 0; mi < 2; ++mi) {                                       \
            MMA_F16(acc[mi][2 * np],     aF[S][mi], bF[S][np].x, bF[S][np].y); \
            MMA_F16(acc[mi][2 * np + 1], aF[S][mi], bF[S][np].z, bF[S][np].w); \
        }                                                                      \
    }

    LOAD_MAIN(0, 0);

#pragma unroll 2
    for (int kc = 0; kc < 128; ++kc) {
        const int s = kc & 1;
        if (kc < 127) { LOAD_MAIN(kc + 1, s ^ 1); }
        else          { LOAD_TAIL(0, s ^ 1); }
        DO_MMAS(s);
    }
#pragma unroll 2
    for (int t = 0; t < 16; ++t) {
        const int s = (128 + t) & 1;
        if (t < 15) LOAD_TAIL(t + 1, s ^ 1);
        DO_MMAS(s);
    }
#undef LOAD_MAIN
#undef LOAD_TAIL
#undef DO_MMAS

    // epilogue: D[m][oc] -> out[n, oc, oh, ow] + bias
#pragma unroll
    for (int mi = 0; mi < 2; ++mi) {
        int m   = m0 + warpm * 32 + mi * 16 + g;
        int n16 = m >> 12;
        int rem = m & 4095;
#pragma unroll
        for (int ni = 0; ni < 8; ++ni) {
            int oc = nt * 128 + wn * 64 + ni * 8 + tg * 2;
            float bv0 = __ldg(&bias[oc]);
            float bv1 = __ldg(&bias[oc + 1]);
            float* p = out + (((size_t)(n16 * COUT + oc)) << 12) + rem;
            p[0]    = acc[mi][ni][0] + bv0;   // (m,   oc)
            p[4096] = acc[mi][ni][1] + bv1;   // (m,   oc+1)
            p[8]    = acc[mi][ni][2] + bv0;   // (m+8, oc)
            p[4104] = acc[mi][ni][3] + bv1;   // (m+8, oc+1)
        }
    }
}

// ---------------------------------------------------------------------------
extern "C" void kernel_launch(void* const* d_in, const int* in_sizes, int n_in,
                              void* d_out, int out_size) {
    const float* x    = (const float*)d_in[0];
    const float* w    = (const float*)d_in[1];
    const float* bias = (const float*)d_in[2];
    const float* bk   = (const float*)d_in[3];
    float* out = (float*)d_out;
    (void)in_sizes; (void)n_in; (void)out_size;

    prep_k_kernel<<<1, 32>>>(bk);

    blur_kernel<<<dim3(NIMG * CIN, 4), 256>>>(x);

    bprep_kernel<<<(4 * NKC * 8 * 32 + 255) / 256, 256>>>(w);

    dim3 grid(COUT / 128, MDIM / 128);      // (4, 512): n fast -> A L2 reuse
    gemm_kernel<<<grid, 256>>>(bias, out);
}